// round 7
// baseline (speedup 1.0000x reference)
#include <cuda_runtime.h>
#include <cuda_bf16.h>

#define T_DIM 1024
#define B_DIM 64
#define H_DIM 1024
#define OSPLIT 32                 // o-range per k1 block (R3 winner)

// k2 persistent-stealing geometry
#define ROWS_PER_CHUNK 32         // 8 warps x 4 rows
#define CHUNKS_PER_B   (T_DIM / ROWS_PER_CHUNK)     // 32
#define NCHUNK         (B_DIM * CHUNKS_PER_B)       // 2048
#define K2_GRID        304        // ~2x SM count; extras exit after one steal

// Scratch (allocation-free rule: __device__ globals)
__device__ float g_partial[OSPLIT * B_DIM * H_DIM];  // 8 MB: [s][b][h]
__device__ float g_v[B_DIM * H_DIM];                 // 256 KB
__device__ float g_energies[B_DIM * T_DIM];          // 256 KB: [b][t]
__device__ unsigned g_ctr;                           // k2 work counter

// ---------------------------------------------------------------------------
// k1: partial[s][b][h] = sum_{o in s-range} hid[b][o] * W[o][h]
// grid (H/256, 32, 2), 256 threads. W read exactly once. (R3 config)
// ---------------------------------------------------------------------------
__global__ void __launch_bounds__(256) k1_proj_partial(
    const float* __restrict__ hid, const float* __restrict__ W)
{
    const int h  = blockIdx.x * 256 + threadIdx.x;
    const int o0 = blockIdx.y * OSPLIT;
    const int b0 = blockIdx.z * 32;

    __shared__ float sh[32 * OSPLIT];
    for (int i = threadIdx.x; i < 32 * OSPLIT; i += 256) {
        int bb = i >> 5;
        int oo = i & 31;
        sh[i] = hid[(b0 + bb) * H_DIM + o0 + oo];
    }
    __syncthreads();

    float w[OSPLIT];
#pragma unroll
    for (int oo = 0; oo < OSPLIT; oo++)
        w[oo] = W[(o0 + oo) * H_DIM + h];

    float* part = g_partial + blockIdx.y * (B_DIM * H_DIM) + h;

#pragma unroll
    for (int bb = 0; bb < 32; bb++) {
        const float4* s4 = reinterpret_cast<const float4*>(sh + bb * OSPLIT);
        float acc = 0.f;
#pragma unroll
        for (int q = 0; q < OSPLIT / 4; q++) {
            float4 x = s4[q];
            acc += x.x * w[4 * q + 0] + x.y * w[4 * q + 1]
                 + x.z * w[4 * q + 2] + x.w * w[4 * q + 3];
        }
        part[(b0 + bb) * H_DIM] = acc;
    }
}

// ---------------------------------------------------------------------------
// k1b: v[i] = sum_s partial[s][i]; also resets k2's steal counter
// (stream order guarantees the reset lands before k2 starts).
// ---------------------------------------------------------------------------
__global__ void __launch_bounds__(256) k1b_reduce()
{
    if (blockIdx.x == 0 && threadIdx.x == 0)
        g_ctr = 0;

    int i = blockIdx.x * 256 + threadIdx.x;
    float s = 0.f;
#pragma unroll
    for (int p = 0; p < OSPLIT; p++)
        s += g_partial[p * (B_DIM * H_DIM) + i];
    g_v[i] = s;
}

// ---------------------------------------------------------------------------
// k2: energies[b][t] = <enc[t,b,:], v[b,:]>  — persistent work stealing.
// Item = (b, 32-row t-chunk); warp does 4 rows with v[b] in 8 float4 regs
// and 32 batched LDG.128 (R3's proven inner shape). Stealing kills wave
// quantization: finish-time spread ~ one 2.7us chunk instead of an 11us CTA.
// ---------------------------------------------------------------------------
__global__ void __launch_bounds__(256) k2_energies(const float* __restrict__ enc)
{
    const int warp = threadIdx.x >> 5;
    const int lane = threadIdx.x & 31;
    __shared__ unsigned s_item;

    const size_t row_stride4 = (size_t)B_DIM * H_DIM / 4;   // float4 units

    for (;;) {
        __syncthreads();                 // protect s_item from prev iter
        if (threadIdx.x == 0)
            s_item = atomicAdd(&g_ctr, 1u);
        __syncthreads();
        const unsigned item = s_item;
        if (item >= NCHUNK) break;       // uniform exit

        const int b  = item / CHUNKS_PER_B;
        const int t0 = (item % CHUNKS_PER_B) * ROWS_PER_CHUNK + warp * 4;

        // v[b] -> 8 float4 regs (L2-hot; amortized over 4 rows)
        const float4* v4 = reinterpret_cast<const float4*>(g_v + b * H_DIM);
        float4 v[8];
#pragma unroll
        for (int k = 0; k < 8; k++)
            v[k] = v4[lane + 32 * k];

        const float4* e4 = reinterpret_cast<const float4*>(
            enc + ((size_t)t0 * B_DIM + b) * H_DIM) + lane;

        // 4 rows, fully batched loads (4 x 8 independent LDG.128)
        float acc0 = 0.f, acc1 = 0.f, acc2 = 0.f, acc3 = 0.f;
#pragma unroll
        for (int k = 0; k < 8; k++) {
            float4 x0 = e4[0 * row_stride4 + 32 * k];
            float4 x1 = e4[1 * row_stride4 + 32 * k];
            float4 x2 = e4[2 * row_stride4 + 32 * k];
            float4 x3 = e4[3 * row_stride4 + 32 * k];
            acc0 += x0.x * v[k].x + x0.y * v[k].y + x0.z * v[k].z + x0.w * v[k].w;
            acc1 += x1.x * v[k].x + x1.y * v[k].y + x1.z * v[k].z + x1.w * v[k].w;
            acc2 += x2.x * v[k].x + x2.y * v[k].y + x2.z * v[k].z + x2.w * v[k].w;
            acc3 += x3.x * v[k].x + x3.y * v[k].y + x3.z * v[k].z + x3.w * v[k].w;
        }
#pragma unroll
        for (int off = 16; off; off >>= 1) {
            acc0 += __shfl_xor_sync(0xffffffffu, acc0, off);
            acc1 += __shfl_xor_sync(0xffffffffu, acc1, off);
            acc2 += __shfl_xor_sync(0xffffffffu, acc2, off);
            acc3 += __shfl_xor_sync(0xffffffffu, acc3, off);
        }
        if (lane == 0) {
            float* eout = g_energies + b * T_DIM + t0;
            eout[0] = acc0;
            eout[1] = acc1;
            eout[2] = acc2;
            eout[3] = acc3;
        }
    }
}

// ---------------------------------------------------------------------------
// k3: softmax over T per row b — warp per row, one block per row (grid 64).
// Bias dropped (softmax shift invariance). (Measured-best shape.)
// ---------------------------------------------------------------------------
__global__ void __launch_bounds__(32) k3_softmax(float* __restrict__ out)
{
    const int lane = threadIdx.x;
    const int b    = blockIdx.x;

    const float4* e4 = reinterpret_cast<const float4*>(g_energies + b * T_DIM);
    float4 vals[8];
#pragma unroll
    for (int k = 0; k < 8; k++)
        vals[k] = e4[lane + 32 * k];

    float m = -1e30f;
#pragma unroll
    for (int k = 0; k < 8; k++)
        m = fmaxf(m, fmaxf(fmaxf(vals[k].x, vals[k].y), fmaxf(vals[k].z, vals[k].w)));
#pragma unroll
    for (int off = 16; off; off >>= 1)
        m = fmaxf(m, __shfl_xor_sync(0xffffffffu, m, off));

    float lsum = 0.f;
#pragma unroll
    for (int k = 0; k < 8; k++) {
        vals[k].x = __expf(vals[k].x - m);
        vals[k].y = __expf(vals[k].y - m);
        vals[k].z = __expf(vals[k].z - m);
        vals[k].w = __expf(vals[k].w - m);
        lsum += vals[k].x + vals[k].y + vals[k].z + vals[k].w;
    }
#pragma unroll
    for (int off = 16; off; off >>= 1)
        lsum += __shfl_xor_sync(0xffffffffu, lsum, off);
    const float inv = 1.f / lsum;

    float4* o4 = reinterpret_cast<float4*>(out + b * T_DIM);
#pragma unroll
    for (int k = 0; k < 8; k++) {
        float4 r = vals[k];
        r.x *= inv; r.y *= inv; r.z *= inv; r.w *= inv;
        o4[lane + 32 * k] = r;
    }
}

// ---------------------------------------------------------------------------
extern "C" void kernel_launch(void* const* d_in, const int* in_sizes, int n_in,
                              void* d_out, int out_size)
{
    const float* hid = (const float*)d_in[0];   // [1, B, H]
    const float* enc = (const float*)d_in[1];   // [T, B, H]
    const float* W   = (const float*)d_in[2];   // [H, H]
    // d_in[3] = bias: dropped — softmax shift-invariance makes it a no-op.
    float* out = (float*)d_out;                 // [B, 1, T]

    k1_proj_partial<<<dim3(H_DIM / 256, OSPLIT, 2), 256>>>(hid, W);
    k1b_reduce<<<(B_DIM * H_DIM) / 256, 256>>>();
    k2_energies<<<K2_GRID, 256>>>(enc);
    k3_softmax<<<B_DIM, 32>>>(out);
}

// round 8
// speedup vs baseline: 1.3318x; 1.3318x over previous
#include <cuda_runtime.h>
#include <cuda_bf16.h>

#define T_DIM 1024
#define B_DIM 64
#define H_DIM 1024
#define OSPLIT 32                 // o-range per k1 block (R3 winner)
#define TPW 8                     // t-rows per warp in k2 (R3 had 16)

// Scratch (allocation-free rule: __device__ globals)
__device__ float g_partial[OSPLIT * B_DIM * H_DIM];  // 8 MB: [s][b][h]
__device__ float g_v[B_DIM * H_DIM];                 // 256 KB
__device__ float g_energies[B_DIM * T_DIM];          // 256 KB: [b][t]

// ---------------------------------------------------------------------------
// k1: partial[s][b][h] = sum_{o in s-range} hid[b][o] * W[o][h]
// grid (H/256, 32, 2), 256 threads. W read exactly once. (R3 config)
// ---------------------------------------------------------------------------
__global__ void __launch_bounds__(256) k1_proj_partial(
    const float* __restrict__ hid, const float* __restrict__ W)
{
    const int h  = blockIdx.x * 256 + threadIdx.x;
    const int o0 = blockIdx.y * OSPLIT;
    const int b0 = blockIdx.z * 32;

    __shared__ float sh[32 * OSPLIT];
    for (int i = threadIdx.x; i < 32 * OSPLIT; i += 256) {
        int bb = i >> 5;
        int oo = i & 31;
        sh[i] = hid[(b0 + bb) * H_DIM + o0 + oo];
    }
    __syncthreads();

    float w[OSPLIT];
#pragma unroll
    for (int oo = 0; oo < OSPLIT; oo++)
        w[oo] = W[(o0 + oo) * H_DIM + h];

    float* part = g_partial + blockIdx.y * (B_DIM * H_DIM) + h;

#pragma unroll
    for (int bb = 0; bb < 32; bb++) {
        const float4* s4 = reinterpret_cast<const float4*>(sh + bb * OSPLIT);
        float acc = 0.f;
#pragma unroll
        for (int q = 0; q < OSPLIT / 4; q++) {
            float4 x = s4[q];
            acc += x.x * w[4 * q + 0] + x.y * w[4 * q + 1]
                 + x.z * w[4 * q + 2] + x.w * w[4 * q + 3];
        }
        part[(b0 + bb) * H_DIM] = acc;
    }
}

// ---------------------------------------------------------------------------
// k1b: v[i] = sum_s partial[s][i]   (deterministic reduction, no atomics)
// ---------------------------------------------------------------------------
__global__ void __launch_bounds__(256) k1b_reduce()
{
    int i = blockIdx.x * 256 + threadIdx.x;  // 65536 total
    float s = 0.f;
#pragma unroll
    for (int p = 0; p < OSPLIT; p++)
        s += g_partial[p * (B_DIM * H_DIM) + i];
    g_v[i] = s;
}

// ---------------------------------------------------------------------------
// k2: energies[b][t] = <enc[t,b,:], v[b,:]>
// R3's proven structure, ONE variable changed: TPW 16 -> 8.
// grid (64 b, 16 t-chunks) = 1024 CTAs (~5.5us each) -> 6.9 waves,
// quantization tail ~1% instead of ~15%. Inner loop identical to R3:
// v in 8 float4 regs, 1-row body, unroll 4 => 32 batched LDG.128 in flight.
// enc loads use __ldcs (pure stream, evict-first).
// ---------------------------------------------------------------------------
__global__ void __launch_bounds__(256) k2_energies(const float* __restrict__ enc)
{
    const int warp = threadIdx.x >> 5;
    const int lane = threadIdx.x & 31;
    const int b    = blockIdx.x;                       // 0..63
    const int t0   = blockIdx.y * (8 * TPW) + warp * TPW;

    // v[b] -> registers (8 L2-hot loads per warp, amortized over TPW rows)
    const float4* v4 = reinterpret_cast<const float4*>(g_v + b * H_DIM);
    float4 v[8];
#pragma unroll
    for (int k = 0; k < 8; k++)
        v[k] = v4[lane + 32 * k];

    // Row pointer for first t; advance by a constant row stride per iter
    const float4* e4 = reinterpret_cast<const float4*>(
        enc + (size_t)(t0 * B_DIM + b) * H_DIM) + lane;
    const size_t row_stride4 = (size_t)B_DIM * H_DIM / 4;   // in float4 units

    float* eout = g_energies + b * T_DIM + t0;

#pragma unroll 4
    for (int i = 0; i < TPW; i++) {
        float acc = 0.f;
#pragma unroll
        for (int k = 0; k < 8; k++) {
            float4 x = __ldcs(e4 + 32 * k);
            acc += x.x * v[k].x + x.y * v[k].y + x.z * v[k].z + x.w * v[k].w;
        }
#pragma unroll
        for (int off = 16; off; off >>= 1)
            acc += __shfl_xor_sync(0xffffffffu, acc, off);
        if (lane == 0)
            eout[i] = acc;
        e4 += row_stride4;
    }
}

// ---------------------------------------------------------------------------
// k3: softmax over T per row b — warp per row, one block per row (grid 64).
// Bias dropped (softmax shift invariance). (Measured-best shape.)
// ---------------------------------------------------------------------------
__global__ void __launch_bounds__(32) k3_softmax(float* __restrict__ out)
{
    const int lane = threadIdx.x;
    const int b    = blockIdx.x;

    const float4* e4 = reinterpret_cast<const float4*>(g_energies + b * T_DIM);
    float4 vals[8];
#pragma unroll
    for (int k = 0; k < 8; k++)
        vals[k] = e4[lane + 32 * k];

    float m = -1e30f;
#pragma unroll
    for (int k = 0; k < 8; k++)
        m = fmaxf(m, fmaxf(fmaxf(vals[k].x, vals[k].y), fmaxf(vals[k].z, vals[k].w)));
#pragma unroll
    for (int off = 16; off; off >>= 1)
        m = fmaxf(m, __shfl_xor_sync(0xffffffffu, m, off));

    float lsum = 0.f;
#pragma unroll
    for (int k = 0; k < 8; k++) {
        vals[k].x = __expf(vals[k].x - m);
        vals[k].y = __expf(vals[k].y - m);
        vals[k].z = __expf(vals[k].z - m);
        vals[k].w = __expf(vals[k].w - m);
        lsum += vals[k].x + vals[k].y + vals[k].z + vals[k].w;
    }
#pragma unroll
    for (int off = 16; off; off >>= 1)
        lsum += __shfl_xor_sync(0xffffffffu, lsum, off);
    const float inv = 1.f / lsum;

    float4* o4 = reinterpret_cast<float4*>(out + b * T_DIM);
#pragma unroll
    for (int k = 0; k < 8; k++) {
        float4 r = vals[k];
        r.x *= inv; r.y *= inv; r.z *= inv; r.w *= inv;
        o4[lane + 32 * k] = r;
    }
}

// ---------------------------------------------------------------------------
extern "C" void kernel_launch(void* const* d_in, const int* in_sizes, int n_in,
                              void* d_out, int out_size)
{
    const float* hid = (const float*)d_in[0];   // [1, B, H]
    const float* enc = (const float*)d_in[1];   // [T, B, H]
    const float* W   = (const float*)d_in[2];   // [H, H]
    // d_in[3] = bias: dropped — softmax shift-invariance makes it a no-op.
    float* out = (float*)d_out;                 // [B, 1, T]

    k1_proj_partial<<<dim3(H_DIM / 256, OSPLIT, 2), 256>>>(hid, W);
    k1b_reduce<<<(B_DIM * H_DIM) / 256, 256>>>();
    k2_energies<<<dim3(B_DIM, T_DIM / (8 * TPW)), 256>>>(enc);
    k3_softmax<<<B_DIM, 32>>>(out);
}